// round 4
// baseline (speedup 1.0000x reference)
#include <cuda_runtime.h>
#include <cuda_bf16.h>
#include <math.h>

// ---------------- static problem config ----------------
#define NB    2
#define CIN   64
#define COUT  128
#define TAPS  27
#define DD    16
#define HH    28
#define WW    28
#define DP    18
#define HP    30
#define WP    30
#define VOX   (DD*HH*WW)         // 12544
#define PTOT  (NB*VOX)           // 25088
#define OC1   81
#define OC1P  96
#define BN_EPS 1e-5f

#define BN2   64                 // position tile
#define NBLK  (PTOT/BN2)         // 392

// f32x2 packed-FMA helpers
#define DUPF(d, s) asm("mov.b64 %0, {%1, %1};" : "=l"(d) : "r"(__float_as_uint(s)))
#define FMA2(a, x, y) asm("fma.rn.f32x2 %0, %1, %2, %0;" : "+l"(a) : "l"(x), "l"(y))

// ---------------- scratch ----------------
__device__ float g_xpt[NB*DP*HP*WP*CIN];       // padded channels-last x
__device__ float g_wofft[TAPS*CIN*OC1P];       // offset weights [tap][c][oc]
__device__ float g_wt[TAPS*CIN*COUT];          // deform weights [tap][c][oc]
__device__ float g_off[OC1*PTOT];              // offsets [ch][pos]
__device__ float g_y[COUT*PTOT];               // pre-BN output [co][pos]
__device__ float g_stats[2*COUT];

// ---------------- K0: pad + transpose to channels-last ----------------
__global__ void k_pad(const float* __restrict__ x) {
    int idx = blockIdx.x * blockDim.x + threadIdx.x;
    const int total = NB*DP*HP*WP*CIN;
    if (idx >= total) return;
    int c = idx % CIN;
    int t = idx / CIN;
    int wx = t % WP; t /= WP;
    int hy = t % HP; t /= HP;
    int dz = t % DP; int n = t / DP;
    float v = 0.f;
    if (dz >= 1 && dz <= DD && hy >= 1 && hy <= HH && wx >= 1 && wx <= WW) {
        v = x[(((n*CIN + c)*DD + (dz-1))*HH + (hy-1))*WW + (wx-1)];
    }
    g_xpt[idx] = v;
}

// ---------------- weight transposes ----------------
__global__ void k_wofft(const float* __restrict__ w_off) {
    int idx = blockIdx.x * blockDim.x + threadIdx.x;
    const int total = TAPS*CIN*OC1P;
    if (idx >= total) return;
    int oc = idx % OC1P;
    int t = idx / OC1P;
    int c = t % CIN;
    int tap = t / CIN;
    float v = 0.f;
    if (oc < OC1) v = w_off[(oc*CIN + c)*TAPS + tap];
    g_wofft[idx] = v;
}

__global__ void k_wtrans(const float* __restrict__ w_conv) {
    int idx = blockIdx.x * blockDim.x + threadIdx.x;
    const int total = TAPS*CIN*COUT;
    if (idx >= total) return;
    int oc = idx % COUT;
    int t = idx / COUT;
    int c = t % CIN;
    int tap = t / CIN;
    g_wt[idx] = w_conv[(oc*CIN + c)*TAPS + tap];
}

// ---------------- K1: offset conv GEMM (96 x 64pos, K=1728) ----------------
// 128 threads, thread tile 6 oc x 8 pos, f32x2 packed accumulators
__global__ __launch_bounds__(128) void k_offconv(const float* __restrict__ b_off) {
    __shared__ float As[CIN*OC1P];   // 24KB [c][oc96]
    __shared__ float Bs[CIN*BN2];    // 16KB [c][pos64]

    const int tid = threadIdx.x;
    const int pos0 = blockIdx.x * BN2;
    const int tx = tid & 7;          // 8 n-groups * 8 pos
    const int ty = tid >> 3;         // 16 m-groups * 6 oc

    // gather role: 4 pos x 8 channels per thread
    const int pg = tid & 15;
    const int cg = tid >> 4;         // 0..7
    int gn[4], gd[4], gh[4], gw[4];
    #pragma unroll
    for (int q = 0; q < 4; ++q) {
        int pos = pos0 + pg*4 + q;
        int n = pos / VOX; int vox = pos % VOX;
        gn[q] = n;
        gd[q] = vox / (HH*WW);
        int r = vox % (HH*WW);
        gh[q] = r / WW; gw[q] = r % WW;
    }

    unsigned long long acc[6][4];
    #pragma unroll
    for (int i = 0; i < 6; ++i)
        #pragma unroll
        for (int j = 0; j < 4; ++j) acc[i][j] = 0ULL;

    for (int tap = 0; tap < TAPS; ++tap) {
        const int kd = tap / 9, kh = (tap / 3) % 3, kw = tap % 3;

        __syncthreads();
        // A fill: 6144 floats = 1536 float4
        {
            const float4* src = (const float4*)(g_wofft + tap*CIN*OC1P);
            float4* dst = (float4*)As;
            #pragma unroll
            for (int i = 0; i < 12; ++i) dst[tid + i*128] = src[tid + i*128];
        }
        // B gather: identity im2col, 4 pos x 8 ch, register transpose
        {
            float val[4][8];
            #pragma unroll
            for (int q = 0; q < 4; ++q) {
                const float* xb = g_xpt + ((((gn[q]*DP + gd[q] + kd)*HP + gh[q] + kh)*WP + gw[q] + kw) << 6) + cg*8;
                float4 x0 = *(const float4*)(xb);
                float4 x1 = *(const float4*)(xb + 4);
                val[q][0]=x0.x; val[q][1]=x0.y; val[q][2]=x0.z; val[q][3]=x0.w;
                val[q][4]=x1.x; val[q][5]=x1.y; val[q][6]=x1.z; val[q][7]=x1.w;
            }
            #pragma unroll
            for (int ch = 0; ch < 8; ++ch)
                *(float4*)&Bs[(cg*8 + ch)*BN2 + pg*4] =
                    make_float4(val[0][ch], val[1][ch], val[2][ch], val[3][ch]);
        }
        __syncthreads();

        #pragma unroll 4
        for (int c = 0; c < CIN; ++c) {
            float2 a0 = *(const float2*)&As[c*OC1P + ty*6];
            float2 a1 = *(const float2*)&As[c*OC1P + ty*6 + 2];
            float2 a2 = *(const float2*)&As[c*OC1P + ty*6 + 4];
            ulonglong2 b0 = *(const ulonglong2*)&Bs[c*BN2 + tx*8];
            ulonglong2 b1 = *(const ulonglong2*)&Bs[c*BN2 + tx*8 + 4];
            unsigned long long bp[4] = {b0.x, b0.y, b1.x, b1.y};
            unsigned long long ad[6];
            DUPF(ad[0], a0.x); DUPF(ad[1], a0.y);
            DUPF(ad[2], a1.x); DUPF(ad[3], a1.y);
            DUPF(ad[4], a2.x); DUPF(ad[5], a2.y);
            #pragma unroll
            for (int i = 0; i < 6; ++i)
                #pragma unroll
                for (int j = 0; j < 4; ++j) FMA2(acc[i][j], ad[i], bp[j]);
        }
    }

    const int pos_out = pos0 + tx*8;
    #pragma unroll
    for (int i = 0; i < 6; ++i) {
        int oc = ty*6 + i;
        if (oc < OC1) {
            float bias = b_off[oc];
            float o[8];
            #pragma unroll
            for (int j = 0; j < 4; ++j) {
                unsigned long long v = acc[i][j];
                o[2*j]   = __uint_as_float((unsigned)v) + bias;
                o[2*j+1] = __uint_as_float((unsigned)(v >> 32)) + bias;
            }
            *(float4*)&g_off[oc*PTOT + pos_out]     = make_float4(o[0], o[1], o[2], o[3]);
            *(float4*)&g_off[oc*PTOT + pos_out + 4] = make_float4(o[4], o[5], o[6], o[7]);
        }
    }
}

// ---------------- K2: deform conv GEMM (128 x 64pos, trilinear gather) -------
// 128 threads, thread tile 8 oc x 8 pos, f32x2 packed accumulators
__global__ __launch_bounds__(128) void k_deform() {
    __shared__ float As[CIN*COUT];   // 32KB [c][oc128]
    __shared__ float Bs[CIN*BN2];    // 16KB [c][pos64]

    const int tid = threadIdx.x;
    const int pos0 = blockIdx.x * BN2;
    const int tx = tid & 7;
    const int ty = tid >> 3;

    const int pg = tid & 15;
    const int cg = tid >> 4;
    int gn[4], gd[4], gh[4], gw[4], gpos[4];
    #pragma unroll
    for (int q = 0; q < 4; ++q) {
        int pos = pos0 + pg*4 + q;
        gpos[q] = pos;
        int n = pos / VOX; int vox = pos % VOX;
        gn[q] = n;
        gd[q] = vox / (HH*WW);
        int r = vox % (HH*WW);
        gh[q] = r / WW; gw[q] = r % WW;
    }

    unsigned long long acc[8][4];
    #pragma unroll
    for (int i = 0; i < 8; ++i)
        #pragma unroll
        for (int j = 0; j < 4; ++j) acc[i][j] = 0ULL;

    for (int tap = 0; tap < TAPS; ++tap) {
        const int kd = tap / 9, kh = (tap / 3) % 3, kw = tap % 3;

        __syncthreads();
        // A fill: 8192 floats = 2048 float4
        {
            const float4* src = (const float4*)(g_wt + tap*CIN*COUT);
            float4* dst = (float4*)As;
            #pragma unroll
            for (int i = 0; i < 16; ++i) dst[tid + i*128] = src[tid + i*128];
        }
        // trilinear gather: 4 pos x 8 channels
        {
            float val[4][8];
            #pragma unroll
            for (int q = 0; q < 4; ++q) {
                float od = g_off[(0*TAPS + tap)*PTOT + gpos[q]];
                float oh = g_off[(1*TAPS + tap)*PTOT + gpos[q]];
                float ow = g_off[(2*TAPS + tap)*PTOT + gpos[q]];
                float pd = od + (float)(gd[q] + kd);
                float ph = oh + (float)(gh[q] + kh);
                float pw = ow + (float)(gw[q] + kw);
                float fpd = floorf(pd), fph = floorf(ph), fpw = floorf(pw);
                int d0 = (int)fpd, h0 = (int)fph, w0 = (int)fpw;
                float fd = pd - fpd, fh = ph - fph, fw = pw - fpw;

                float v0=0,v1=0,v2=0,v3=0,v4=0,v5=0,v6=0,v7=0;
                #pragma unroll
                for (int a = 0; a < 2; ++a) {
                    int ddx = d0 + a;
                    if (ddx < 0 || ddx >= DP) continue;
                    float wa = a ? fd : 1.f - fd;
                    #pragma unroll
                    for (int b = 0; b < 2; ++b) {
                        int hhx = h0 + b;
                        if (hhx < 0 || hhx >= HP) continue;
                        float wb = wa * (b ? fh : 1.f - fh);
                        #pragma unroll
                        for (int cc = 0; cc < 2; ++cc) {
                            int wwx = w0 + cc;
                            if (wwx < 0 || wwx >= WP) continue;
                            float wgt = wb * (cc ? fw : 1.f - fw);
                            const float* p = g_xpt + ((((gn[q]*DP + ddx)*HP + hhx)*WP + wwx) << 6) + cg*8;
                            float4 x0 = *(const float4*)(p);
                            float4 x1 = *(const float4*)(p + 4);
                            v0 += wgt*x0.x; v1 += wgt*x0.y; v2 += wgt*x0.z; v3 += wgt*x0.w;
                            v4 += wgt*x1.x; v5 += wgt*x1.y; v6 += wgt*x1.z; v7 += wgt*x1.w;
                        }
                    }
                }
                val[q][0]=v0; val[q][1]=v1; val[q][2]=v2; val[q][3]=v3;
                val[q][4]=v4; val[q][5]=v5; val[q][6]=v6; val[q][7]=v7;
            }
            #pragma unroll
            for (int ch = 0; ch < 8; ++ch)
                *(float4*)&Bs[(cg*8 + ch)*BN2 + pg*4] =
                    make_float4(val[0][ch], val[1][ch], val[2][ch], val[3][ch]);
        }
        __syncthreads();

        #pragma unroll 4
        for (int c = 0; c < CIN; ++c) {
            float4 a0 = *(const float4*)&As[c*COUT + ty*8];
            float4 a1 = *(const float4*)&As[c*COUT + ty*8 + 4];
            ulonglong2 b0 = *(const ulonglong2*)&Bs[c*BN2 + tx*8];
            ulonglong2 b1 = *(const ulonglong2*)&Bs[c*BN2 + tx*8 + 4];
            unsigned long long bp[4] = {b0.x, b0.y, b1.x, b1.y};
            unsigned long long ad[8];
            DUPF(ad[0], a0.x); DUPF(ad[1], a0.y); DUPF(ad[2], a0.z); DUPF(ad[3], a0.w);
            DUPF(ad[4], a1.x); DUPF(ad[5], a1.y); DUPF(ad[6], a1.z); DUPF(ad[7], a1.w);
            #pragma unroll
            for (int i = 0; i < 8; ++i)
                #pragma unroll
                for (int j = 0; j < 4; ++j) FMA2(acc[i][j], ad[i], bp[j]);
        }
    }

    const int pos_out = pos0 + tx*8;
    #pragma unroll
    for (int i = 0; i < 8; ++i) {
        int oc = ty*8 + i;
        float o[8];
        #pragma unroll
        for (int j = 0; j < 4; ++j) {
            unsigned long long v = acc[i][j];
            o[2*j]   = __uint_as_float((unsigned)v);
            o[2*j+1] = __uint_as_float((unsigned)(v >> 32));
        }
        *(float4*)&g_y[oc*PTOT + pos_out]     = make_float4(o[0], o[1], o[2], o[3]);
        *(float4*)&g_y[oc*PTOT + pos_out + 4] = make_float4(o[4], o[5], o[6], o[7]);
    }
}

// ---------------- K3: per-channel batch stats ----------------
__global__ void k_stats() {
    __shared__ float ss[256], ss2[256];
    const int ch = blockIdx.x;
    const int tid = threadIdx.x;
    const float* y = g_y + ch*PTOT;
    float s = 0.f, s2 = 0.f;
    for (int i = tid; i < PTOT; i += 256) {
        float v = y[i];
        s += v; s2 += v*v;
    }
    ss[tid] = s; ss2[tid] = s2;
    __syncthreads();
    for (int stp = 128; stp > 0; stp >>= 1) {
        if (tid < stp) { ss[tid] += ss[tid+stp]; ss2[tid] += ss2[tid+stp]; }
        __syncthreads();
    }
    if (tid == 0) {
        float mean = ss[0] / (float)PTOT;
        float var = ss2[0] / (float)PTOT - mean*mean;
        g_stats[ch] = mean;
        g_stats[COUT + ch] = rsqrtf(var + BN_EPS);
    }
}

// ---------------- K4: normalize + affine + ReLU ----------------
__global__ void k_norm(const float* __restrict__ gamma, const float* __restrict__ beta,
                       float* __restrict__ out) {
    int idx = blockIdx.x * blockDim.x + threadIdx.x;
    const int total = NB*COUT*VOX;
    if (idx >= total) return;
    int vox = idx % VOX;
    int t = idx / VOX;
    int co = t % COUT;
    int n = t / COUT;
    float v = g_y[co*PTOT + n*VOX + vox];
    float r = (v - g_stats[co]) * g_stats[COUT + co] * gamma[co] + beta[co];
    out[idx] = r > 0.f ? r : 0.f;
}

// ---------------- launch ----------------
extern "C" void kernel_launch(void* const* d_in, const int* in_sizes, int n_in,
                              void* d_out, int out_size) {
    const float* x      = (const float*)d_in[0];
    const float* w_off  = (const float*)d_in[1];
    const float* b_off  = (const float*)d_in[2];
    const float* w_conv = (const float*)d_in[3];
    const float* gamma  = (const float*)d_in[4];
    const float* beta   = (const float*)d_in[5];
    float* out = (float*)d_out;

    {
        int total = NB*DP*HP*WP*CIN;
        k_pad<<<(total + 255)/256, 256>>>(x);
    }
    {
        int total = TAPS*CIN*OC1P;
        k_wofft<<<(total + 255)/256, 256>>>(w_off);
    }
    {
        int total = TAPS*CIN*COUT;
        k_wtrans<<<(total + 255)/256, 256>>>(w_conv);
    }
    k_offconv<<<NBLK, 128>>>(b_off);
    k_deform<<<NBLK, 128>>>();
    k_stats<<<COUT, 256>>>();
    {
        int total = NB*COUT*VOX;
        k_norm<<<(total + 255)/256, 256>>>(gamma, beta, out);
    }
}